// round 2
// baseline (speedup 1.0000x reference)
#include <cuda_runtime.h>
#include <math.h>
#include <stdint.h>

#define BB 2
#define NNPTS 4096
#define CF 64
#define KNN 32
#define NTOT (BB*NNPTS)

// ---------------- scratch (static __device__, no allocs) ----------------
__device__ float  g_K[(size_t)BB*NNPTS*NNPTS];   // 128 MB transport kernel
__device__ float  g_f0n[NTOT*CF];
__device__ float  g_f1n[NTOT*CF];
__device__ float  g_n0[NTOT];
__device__ float  g_n1[NTOT];
__device__ float  g_colsum[NTOT];
__device__ float4 g_w4[NTOT];                    // (b, b*x, b*y, b*z)
__device__ float  g_otflow[NTOT*3];
__device__ int    g_idx[NTOT*KNN];
__device__ float  g_x1[NTOT*32];
__device__ float  g_x2[NTOT*64];

// ---------------- prep: feature normalize, point norms, colsum zero -----
__global__ __launch_bounds__(256)
void prep_kernel(const float* __restrict__ pc0, const float* __restrict__ pc1,
                 const float* __restrict__ f0, const float* __restrict__ f1)
{
    int w    = (blockIdx.x*blockDim.x + threadIdx.x) >> 5;
    int lane = threadIdx.x & 31;
    if (w >= 2*NTOT) return;
    int which = w / NTOT;       // 0: feats0, 1: feats1
    int row   = w % NTOT;
    const float* f = which ? f1 : f0;
    float v0 = f[row*CF + lane];
    float v1 = f[row*CF + 32 + lane];
    float ss = v0*v0 + v1*v1;
    #pragma unroll
    for (int o = 16; o > 0; o >>= 1) ss += __shfl_xor_sync(0xffffffffu, ss, o);
    float inv = rsqrtf(ss + 1e-8f);
    float* out = which ? g_f1n : g_f0n;
    out[row*CF + lane]      = v0*inv;
    out[row*CF + 32 + lane] = v1*inv;
    if (lane == 0) {
        const float* pc = which ? pc1 : pc0;
        float x = pc[row*3+0], y = pc[row*3+1], z = pc[row*3+2];
        float n2 = x*x + y*y + z*z;
        if (which) g_n1[row] = n2;
        else { g_n0[row] = n2; g_colsum[row] = 0.f; }
    }
}

// ---------------- K = exp(-(1 - f0n.f1n)/eps) * (sqdist<100), + colsums --
__global__ __launch_bounds__(256)
void kmat_kernel(const float* __restrict__ pc0, const float* __restrict__ pc1,
                 const float* __restrict__ epsilon)
{
    __shared__ float As[64][64];   // k-major: As[k][row]
    __shared__ float Bs[64][64];
    __shared__ float P0[3][64], P1[3][64];
    __shared__ float N0s[64], N1s[64];
    __shared__ float colpart[64];

    int bz = blockIdx.z;
    int row0 = blockIdx.y*64, col0 = blockIdx.x*64;
    int tid = threadIdx.x;

    {   // feature tiles, transpose into k-major smem
        int r = tid & 63, q = tid >> 6;                 // q in 0..3
        const float* a = g_f0n + (size_t)(bz*NNPTS + row0 + r)*CF + q*16;
        const float* b = g_f1n + (size_t)(bz*NNPTS + col0 + r)*CF + q*16;
        #pragma unroll
        for (int i = 0; i < 4; i++) {
            float4 va = *(const float4*)(a + 4*i);
            float4 vb = *(const float4*)(b + 4*i);
            int k = q*16 + 4*i;
            As[k+0][r]=va.x; As[k+1][r]=va.y; As[k+2][r]=va.z; As[k+3][r]=va.w;
            Bs[k+0][r]=vb.x; Bs[k+1][r]=vb.y; Bs[k+2][r]=vb.z; Bs[k+3][r]=vb.w;
        }
    }
    if (tid < 64) {
        int r = tid;
        #pragma unroll
        for (int d = 0; d < 3; d++) P0[d][r] = pc0[(bz*NNPTS+row0+r)*3 + d];
        N0s[r] = g_n0[bz*NNPTS + row0 + r];
        colpart[r] = 0.f;
    } else if (tid < 128) {
        int r = tid - 64;
        #pragma unroll
        for (int d = 0; d < 3; d++) P1[d][r] = pc1[(bz*NNPTS+col0+r)*3 + d];
        N1s[r] = g_n1[bz*NNPTS + col0 + r];
    }
    __syncthreads();

    int rb = (tid >> 4)*4, cb = (tid & 15)*4;
    float acc[4][4];  float accp[4][4];
    #pragma unroll
    for (int i=0;i<4;i++) { acc[i][0]=acc[i][1]=acc[i][2]=acc[i][3]=0.f;
                            accp[i][0]=accp[i][1]=accp[i][2]=accp[i][3]=0.f; }
    #pragma unroll 4
    for (int k = 0; k < 64; k++) {
        float4 a = *(const float4*)&As[k][rb];
        float4 b = *(const float4*)&Bs[k][cb];
        float ar[4] = {a.x,a.y,a.z,a.w}, br[4] = {b.x,b.y,b.z,b.w};
        #pragma unroll
        for (int i=0;i<4;i++)
            #pragma unroll
            for (int j=0;j<4;j++) acc[i][j] = fmaf(ar[i], br[j], acc[i][j]);
    }
    #pragma unroll
    for (int k = 0; k < 3; k++) {
        float4 a = *(const float4*)&P0[k][rb];
        float4 b = *(const float4*)&P1[k][cb];
        float ar[4] = {a.x,a.y,a.z,a.w}, br[4] = {b.x,b.y,b.z,b.w};
        #pragma unroll
        for (int i=0;i<4;i++)
            #pragma unroll
            for (int j=0;j<4;j++) accp[i][j] = fmaf(ar[i], br[j], accp[i][j]);
    }

    float eps = expf(epsilon[0]) + 0.025f;
    float inv_eps = 1.0f/eps;
    float cs[4] = {0.f,0.f,0.f,0.f};
    #pragma unroll
    for (int i = 0; i < 4; i++) {
        float n0v = N0s[rb+i];
        float kv[4];
        #pragma unroll
        for (int j = 0; j < 4; j++) {
            float sqd = n0v + N1s[cb+j] - 2.0f*accp[i][j];
            float Cv  = 1.0f - acc[i][j];
            float v   = (sqd < 100.0f) ? expf(-Cv*inv_eps) : 0.0f;
            kv[j] = v; cs[j] += v;
        }
        float4 o = make_float4(kv[0],kv[1],kv[2],kv[3]);
        *(float4*)&g_K[((size_t)(bz*NNPTS) + row0 + rb + i)*NNPTS + col0 + cb] = o;
    }
    #pragma unroll
    for (int j = 0; j < 4; j++) atomicAdd(&colpart[cb+j], cs[j]);
    __syncthreads();
    if (tid < 64) atomicAdd(&g_colsum[bz*NNPTS + col0 + tid], colpart[tid]);
}

// ---------------- b = (prob2/(K^T a + 1e-8))^power, packed with pc1 ------
__global__ __launch_bounds__(256)
void bvec_kernel(const float* __restrict__ pc1,
                 const float* __restrict__ gamma, const float* __restrict__ epsilon)
{
    int i = blockIdx.x*blockDim.x + threadIdx.x;
    if (i >= NTOT) return;
    float eps = expf(epsilon[0]) + 0.025f;
    float gam = expf(gamma[0]);
    float power = gam/(gam+eps);
    float kta = g_colsum[i] * (1.0f/NNPTS);
    float b = powf((1.0f/NNPTS)/(kta + 1e-8f), power);
    g_w4[i] = make_float4(b, b*pc1[i*3+0], b*pc1[i*3+1], b*pc1[i*3+2]);
}

// ---------------- row pass: Kb, K b pc1 -> ot_flow ------------------------
// grid = NTOT/8 blocks, 256 threads. Dynamic smem: 4096 float4 (w, transposed
// by col%4 so the 4 per-thread w loads are conflict-free LDS.128).
__global__ __launch_bounds__(256)
void rowpass_kernel(const float* __restrict__ pc0,
                    const float* __restrict__ gamma, const float* __restrict__ epsilon)
{
    extern __shared__ float4 wsm[];    // [4][1024]
    __shared__ float rbuf[8][4][4];
    int tid = threadIdx.x;
    int base = blockIdx.x * 8;
    int bz = base / NNPTS;
    const float4* wg = g_w4 + bz*NNPTS;
    for (int c = tid; c < NNPTS; c += 256)
        wsm[(c & 3)*1024 + (c >> 2)] = wg[c];
    __syncthreads();

    int wid = tid >> 5, lane = tid & 31;
    #pragma unroll 1
    for (int half = 0; half < 2; half++) {
        int r0 = base + half*4;
        const float4* K0 = (const float4*)(g_K + (size_t)(r0+0)*NNPTS);
        const float4* K1 = (const float4*)(g_K + (size_t)(r0+1)*NNPTS);
        const float4* K2 = (const float4*)(g_K + (size_t)(r0+2)*NNPTS);
        const float4* K3 = (const float4*)(g_K + (size_t)(r0+3)*NNPTS);
        float acc[4][4];
        #pragma unroll
        for (int r = 0; r < 4; r++)
            acc[r][0]=acc[r][1]=acc[r][2]=acc[r][3]=0.f;
        #pragma unroll
        for (int i = 0; i < 4; i++) {
            int f = tid + i*256;
            float4 w0 = wsm[f],       w1 = wsm[1024+f];
            float4 w2 = wsm[2048+f],  w3 = wsm[3072+f];
            float4 kr[4] = { K0[f], K1[f], K2[f], K3[f] };
            #pragma unroll
            for (int r = 0; r < 4; r++) {
                float4 k = kr[r];
                acc[r][0] = fmaf(k.x,w0.x, fmaf(k.y,w1.x, fmaf(k.z,w2.x, fmaf(k.w,w3.x, acc[r][0]))));
                acc[r][1] = fmaf(k.x,w0.y, fmaf(k.y,w1.y, fmaf(k.z,w2.y, fmaf(k.w,w3.y, acc[r][1]))));
                acc[r][2] = fmaf(k.x,w0.z, fmaf(k.y,w1.z, fmaf(k.z,w2.z, fmaf(k.w,w3.z, acc[r][2]))));
                acc[r][3] = fmaf(k.x,w0.w, fmaf(k.y,w1.w, fmaf(k.z,w2.w, fmaf(k.w,w3.w, acc[r][3]))));
            }
        }
        #pragma unroll
        for (int r = 0; r < 4; r++) {
            #pragma unroll
            for (int o = 16; o > 0; o >>= 1) {
                acc[r][0] += __shfl_xor_sync(0xffffffffu, acc[r][0], o);
                acc[r][1] += __shfl_xor_sync(0xffffffffu, acc[r][1], o);
                acc[r][2] += __shfl_xor_sync(0xffffffffu, acc[r][2], o);
                acc[r][3] += __shfl_xor_sync(0xffffffffu, acc[r][3], o);
            }
            if (lane == 0) {
                rbuf[wid][r][0]=acc[r][0]; rbuf[wid][r][1]=acc[r][1];
                rbuf[wid][r][2]=acc[r][2]; rbuf[wid][r][3]=acc[r][3];
            }
        }
        __syncthreads();
        if (tid < 4) {
            int r = tid;
            float Kb=0.f,Sx=0.f,Sy=0.f,Sz=0.f;
            #pragma unroll
            for (int w = 0; w < 8; w++) {
                Kb += rbuf[w][r][0]; Sx += rbuf[w][r][1];
                Sy += rbuf[w][r][2]; Sz += rbuf[w][r][3];
            }
            float eps = expf(epsilon[0]) + 0.025f;
            float gam = expf(gamma[0]);
            float power = gam/(gam+eps);
            float a  = powf((1.0f/NNPTS)/(Kb + 1e-8f), power);
            float rs = a*Kb;
            float inv = 1.0f/(rs + 1e-8f);
            int row = r0 + r;
            g_otflow[row*3+0] = a*Sx*inv - pc0[row*3+0];
            g_otflow[row*3+1] = a*Sy*inv - pc0[row*3+1];
            g_otflow[row*3+2] = a*Sz*inv - pc0[row*3+2];
        }
        __syncthreads();
    }
}

// ---------------- KNN: radix-select 32 smallest sqdists -------------------
// grid = NTOT/8, 256 threads, 8 queries per block.
// Dynamic smem: 4096 float4 point cache (x,y,z,|p|^2) = 64 KB.
__global__ __launch_bounds__(256)
void knn_kernel(const float* __restrict__ pc0)
{
    extern __shared__ float4 pts[];          // 4096 float4
    __shared__ int s_hist[8][256];           // per-warp hists
    __shared__ int s_wsum[8];
    __shared__ unsigned s_prefix;
    __shared__ int s_krem, s_cl, s_ct;
    __shared__ int s_out[KNN];
    __shared__ int s_tie[64];

    int tid = threadIdx.x;
    int wid = tid >> 5, lane = tid & 31;
    int base = blockIdx.x * 8;
    int bz = base / NNPTS;
    const float* pc = pc0 + bz*NNPTS*3;
    const float* n0 = g_n0 + bz*NNPTS;

    for (int i = tid; i < NNPTS; i += 256)
        pts[i] = make_float4(pc[i*3+0], pc[i*3+1], pc[i*3+2], n0[i]);
    __syncthreads();

    for (int q = 0; q < 8; q++) {
        int node = base + q;
        float4 qp = pts[node - bz*NNPTS];

        unsigned key[16];
        #pragma unroll
        for (int i = 0; i < 16; i++) {
            float4 p = pts[i*256 + tid];
            float dot = p.x*qp.x + p.y*qp.y + p.z*qp.z;
            float d = qp.w + p.w - 2.0f*dot;
            unsigned u = __float_as_uint(d);
            key[i] = (u & 0x80000000u) ? ~u : (u | 0x80000000u);
        }

        if (tid == 0) { s_prefix = 0u; s_krem = KNN; s_cl = 0; s_ct = 0; }
        __syncthreads();

        for (int r = 0; r < 4; r++) {
            int shift = 24 - 8*r;
            #pragma unroll
            for (int w = 0; w < 8; w++) s_hist[w][tid] = 0;
            __syncthreads();
            unsigned pref = s_prefix;
            int krem = s_krem;
            unsigned msk = (r == 0) ? 0u : (0xFFFFFFFFu << (32 - 8*r));
            #pragma unroll
            for (int i = 0; i < 16; i++) {
                unsigned bin = (key[i] >> shift) & 255u;
                bool valid = ((key[i] & msk) == (pref & msk));
                unsigned tag = valid ? bin : (0x100u + (unsigned)lane);
                unsigned grp = __match_any_sync(0xffffffffu, tag);
                if (valid && lane == (__ffs(grp) - 1))
                    atomicAdd(&s_hist[wid][bin], __popc(grp));
            }
            __syncthreads();
            // parallel scan over 256 bins
            int c = 0;
            #pragma unroll
            for (int w = 0; w < 8; w++) c += s_hist[w][tid];
            int v = c;
            #pragma unroll
            for (int o = 1; o < 32; o <<= 1) {
                int n = __shfl_up_sync(0xffffffffu, v, o);
                if (lane >= o) v += n;
            }
            if (lane == 31) s_wsum[wid] = v;
            __syncthreads();
            if (tid == 0) {
                int accum = 0;
                #pragma unroll
                for (int w = 0; w < 8; w++) { int t = s_wsum[w]; s_wsum[w] = accum; accum += t; }
            }
            __syncthreads();
            int incl = v + s_wsum[wid];
            int excl = incl - c;
            if (excl < krem && krem <= incl) {
                s_prefix = pref | ((unsigned)tid << shift);
                s_krem = krem - excl;
            }
            __syncthreads();
        }

        unsigned pivot = s_prefix;
        #pragma unroll
        for (int i = 0; i < 16; i++) {
            unsigned u = key[i];
            if (u < pivot)       { int p = atomicAdd(&s_cl, 1); s_out[p] = i*256 + tid; }
            else if (u == pivot) { int t = atomicAdd(&s_ct, 1); if (t < 64) s_tie[t] = i*256 + tid; }
        }
        __syncthreads();
        if (tid == 0) {
            int cl = s_cl;
            int nt = (s_ct < 64) ? s_ct : 64;
            int need = KNN - cl;             // ties by lowest index (jax tie-break)
            for (int s = 0; s < need; s++) {
                int best = 0x7FFFFFFF, bi = 0;
                for (int t = 0; t < nt; t++) if (s_tie[t] < best) { best = s_tie[t]; bi = t; }
                s_tie[bi] = 0x7FFFFFFF;
                s_out[cl + s] = best;
            }
        }
        __syncthreads();
        if (tid < KNN) g_idx[node*KNN + tid] = s_out[tid];
        __syncthreads();
    }
}

// ---------------- fused set-conv layer (edge GEMM + max + 2 dense) -------
__device__ __forceinline__ float lrelu(float x){ return (x > 0.f) ? x : 0.1f*x; }

template<int LAYER>
__global__ __launch_bounds__(128)
void conv_kernel(const float* __restrict__ pc0,
                 const float* __restrict__ W1, const float* __restrict__ B1,
                 const float* __restrict__ W2, const float* __restrict__ B2,
                 const float* __restrict__ W3, const float* __restrict__ B3,
                 const float* __restrict__ Wfc, const float* __restrict__ Bfc,
                 float* __restrict__ dout)
{
    constexpr int CIN  = (LAYER==0) ? 3 : (LAYER==1) ? 32 : 64;
    constexpr int C    = (LAYER==0) ? 32 : (LAYER==1) ? 64 : 128;
    constexpr bool FIN = (LAYER==2);
    constexpr int NPB  = 128 / C;
    constexpr int KTOT = CIN + 3;
    constexpr int K4   = (KTOT + 3) & ~3;
    constexpr int KM   = KTOT & ~3;

    __shared__ __align__(16) float in_s[NPB][KNN][K4];
    __shared__ float h1[NPB][C];
    __shared__ float h2[NPB][C];
    __shared__ int   nb_s[NPB][KNN];

    const float* feat_in = (LAYER==0) ? g_otflow : (LAYER==1) ? g_x1 : g_x2;
    float* feat_out = (LAYER==0) ? g_x1 : g_x2;

    int tid = threadIdx.x;
    int g = tid / C, c = tid % C;
    int node = blockIdx.x * NPB + g;
    int b = node / NNPTS;

    if (c < KNN) nb_s[g][c] = g_idx[node*KNN + c];
    __syncthreads();

    for (int e = c; e < KNN*KTOT; e += C) {
        int j = e / KTOT, k = e % KTOT;
        int nb = nb_s[g][j];
        float v;
        if (k < CIN) v = feat_in[(size_t)(b*NNPTS + nb)*CIN + k];
        else {
            int d = k - CIN;
            v = pc0[(b*NNPTS + nb)*3 + d] - pc0[node*3 + d];
        }
        in_s[g][j][k] = v;
    }
    __syncthreads();

    // edge layer: acc over KNN neighbors, channel c
    float acc[KNN];
    float bias1 = B1[c];
    #pragma unroll
    for (int j = 0; j < KNN; j++) acc[j] = bias1;
    for (int k = 0; k < KM; k += 4) {
        float w0 = W1[(k+0)*C + c];
        float w1 = W1[(k+1)*C + c];
        float w2 = W1[(k+2)*C + c];
        float w3 = W1[(k+3)*C + c];
        #pragma unroll
        for (int j = 0; j < KNN; j++) {
            float4 iv = *(const float4*)&in_s[g][j][k];
            acc[j] = fmaf(iv.x, w0, acc[j]);
            acc[j] = fmaf(iv.y, w1, acc[j]);
            acc[j] = fmaf(iv.z, w2, acc[j]);
            acc[j] = fmaf(iv.w, w3, acc[j]);
        }
    }
    for (int k = KM; k < KTOT; k++) {
        float w = W1[k*C + c];
        #pragma unroll
        for (int j = 0; j < KNN; j++) acc[j] = fmaf(in_s[g][j][k], w, acc[j]);
    }
    float mx = -3.4e38f;
    #pragma unroll
    for (int j = 0; j < KNN; j++) mx = fmaxf(mx, lrelu(acc[j]));
    h1[g][c] = mx;
    __syncthreads();

    float a2 = B2[c];
    for (int k = 0; k < C; k++) a2 = fmaf(h1[g][k], W2[k*C + c], a2);
    a2 = lrelu(a2);
    h2[g][c] = a2;
    __syncthreads();

    float a3 = B3[c];
    for (int k = 0; k < C; k++) a3 = fmaf(h2[g][k], W3[k*C + c], a3);
    a3 = lrelu(a3);

    if (!FIN) {
        feat_out[(size_t)node*C + c] = a3;
    } else {
        h1[g][c] = a3;
        __syncthreads();
        if (c < 3) {
            float o = Bfc[c];
            for (int k = 0; k < C; k++) o = fmaf(h1[g][k], Wfc[k*3 + c], o);
            dout[node*3 + c] = g_otflow[node*3 + c] + o;
        }
    }
}

// ---------------- launch --------------------------------------------------
extern "C" void kernel_launch(void* const* d_in, const int* in_sizes, int n_in,
                              void* d_out, int out_size)
{
    const float* pc0   = (const float*)d_in[0];
    const float* pc1   = (const float*)d_in[1];
    const float* f0    = (const float*)d_in[2];
    const float* f1    = (const float*)d_in[3];
    const float* gamma = (const float*)d_in[4];
    const float* eps   = (const float*)d_in[5];
    const float* w1_1=(const float*)d_in[6],  *b1_1=(const float*)d_in[7];
    const float* w1_2=(const float*)d_in[8],  *b1_2=(const float*)d_in[9];
    const float* w1_3=(const float*)d_in[10], *b1_3=(const float*)d_in[11];
    const float* w2_1=(const float*)d_in[12], *b2_1=(const float*)d_in[13];
    const float* w2_2=(const float*)d_in[14], *b2_2=(const float*)d_in[15];
    const float* w2_3=(const float*)d_in[16], *b2_3=(const float*)d_in[17];
    const float* w3_1=(const float*)d_in[18], *b3_1=(const float*)d_in[19];
    const float* w3_2=(const float*)d_in[20], *b3_2=(const float*)d_in[21];
    const float* w3_3=(const float*)d_in[22], *b3_3=(const float*)d_in[23];
    const float* wfc =(const float*)d_in[24], *bfc =(const float*)d_in[25];
    float* out = (float*)d_out;

    static int attr_done = 0;
    if (!attr_done) {
        cudaFuncSetAttribute(knn_kernel, cudaFuncAttributeMaxDynamicSharedMemorySize, 65536);
        cudaFuncSetAttribute(rowpass_kernel, cudaFuncAttributeMaxDynamicSharedMemorySize, 65536);
        attr_done = 1;
    }

    prep_kernel<<<2048, 256>>>(pc0, pc1, f0, f1);
    kmat_kernel<<<dim3(NNPTS/64, NNPTS/64, BB), 256>>>(pc0, pc1, eps);
    bvec_kernel<<<(NTOT + 255)/256, 256>>>(pc1, gamma, eps);
    rowpass_kernel<<<NTOT/8, 256, 65536>>>(pc0, gamma, eps);
    knn_kernel<<<NTOT/8, 256, 65536>>>(pc0);
    conv_kernel<0><<<NTOT/4, 128>>>(pc0, w1_1,b1_1, w1_2,b1_2, w1_3,b1_3, wfc,bfc, out);
    conv_kernel<1><<<NTOT/2, 128>>>(pc0, w2_1,b2_1, w2_2,b2_2, w2_3,b2_3, wfc,bfc, out);
    conv_kernel<2><<<NTOT,   128>>>(pc0, w3_1,b3_1, w3_2,b3_2, w3_3,b3_3, wfc,bfc, out);
}

// round 3
// speedup vs baseline: 1.1189x; 1.1189x over previous
#include <cuda_runtime.h>
#include <math.h>
#include <stdint.h>

#define BB 2
#define NNPTS 4096
#define CF 64
#define KNN 32
#define NTOT (BB*NNPTS)

// ---------------- scratch (static __device__, no allocs) ----------------
__device__ float  g_K[(size_t)BB*NNPTS*NNPTS];   // 128 MB transport kernel
__device__ float  g_f0n[NTOT*CF];
__device__ float  g_f1n[NTOT*CF];
__device__ float  g_n0[NTOT];
__device__ float  g_n1[NTOT];
__device__ float  g_colsum[NTOT];
__device__ float4 g_w4t[NTOT];                   // transposed (b, b*x, b*y, b*z)
__device__ float  g_otflow[NTOT*3];
__device__ int    g_idx[NTOT*KNN];
__device__ float  g_x1[NTOT*32];
__device__ float  g_x2[NTOT*64];

// ---------------- prep: feature normalize, point norms, colsum zero -----
__global__ __launch_bounds__(256)
void prep_kernel(const float* __restrict__ pc0, const float* __restrict__ pc1,
                 const float* __restrict__ f0, const float* __restrict__ f1)
{
    int w    = (blockIdx.x*blockDim.x + threadIdx.x) >> 5;
    int lane = threadIdx.x & 31;
    if (w >= 2*NTOT) return;
    int which = w / NTOT;       // 0: feats0, 1: feats1
    int row   = w % NTOT;
    const float* f = which ? f1 : f0;
    float v0 = f[row*CF + lane];
    float v1 = f[row*CF + 32 + lane];
    float ss = v0*v0 + v1*v1;
    #pragma unroll
    for (int o = 16; o > 0; o >>= 1) ss += __shfl_xor_sync(0xffffffffu, ss, o);
    float inv = rsqrtf(ss + 1e-8f);
    float* out = which ? g_f1n : g_f0n;
    out[row*CF + lane]      = v0*inv;
    out[row*CF + 32 + lane] = v1*inv;
    if (lane == 0) {
        const float* pc = which ? pc1 : pc0;
        float x = pc[row*3+0], y = pc[row*3+1], z = pc[row*3+2];
        float n2 = x*x + y*y + z*z;
        if (which) g_n1[row] = n2;
        else { g_n0[row] = n2; g_colsum[row] = 0.f; }
    }
}

// ---------------- K = exp(-(1 - f0n.f1n)/eps) * (sqdist<100), + colsums --
__global__ __launch_bounds__(256)
void kmat_kernel(const float* __restrict__ pc0, const float* __restrict__ pc1,
                 const float* __restrict__ epsilon)
{
    __shared__ float As[64][64];   // k-major: As[k][row]
    __shared__ float Bs[64][64];
    __shared__ float P0[3][64], P1[3][64];
    __shared__ float N0s[64], N1s[64];
    __shared__ float colpart[64];

    int bz = blockIdx.z;
    int row0 = blockIdx.y*64, col0 = blockIdx.x*64;
    int tid = threadIdx.x;

    {   // feature tiles, transpose into k-major smem
        int r = tid & 63, q = tid >> 6;                 // q in 0..3
        const float* a = g_f0n + (size_t)(bz*NNPTS + row0 + r)*CF + q*16;
        const float* b = g_f1n + (size_t)(bz*NNPTS + col0 + r)*CF + q*16;
        #pragma unroll
        for (int i = 0; i < 4; i++) {
            float4 va = *(const float4*)(a + 4*i);
            float4 vb = *(const float4*)(b + 4*i);
            int k = q*16 + 4*i;
            As[k+0][r]=va.x; As[k+1][r]=va.y; As[k+2][r]=va.z; As[k+3][r]=va.w;
            Bs[k+0][r]=vb.x; Bs[k+1][r]=vb.y; Bs[k+2][r]=vb.z; Bs[k+3][r]=vb.w;
        }
    }
    if (tid < 64) {
        int r = tid;
        #pragma unroll
        for (int d = 0; d < 3; d++) P0[d][r] = pc0[(bz*NNPTS+row0+r)*3 + d];
        N0s[r] = g_n0[bz*NNPTS + row0 + r];
        colpart[r] = 0.f;
    } else if (tid < 128) {
        int r = tid - 64;
        #pragma unroll
        for (int d = 0; d < 3; d++) P1[d][r] = pc1[(bz*NNPTS+col0+r)*3 + d];
        N1s[r] = g_n1[bz*NNPTS + col0 + r];
    }
    __syncthreads();

    int rb = (tid >> 4)*4, cb = (tid & 15)*4;
    float acc[4][4];  float accp[4][4];
    #pragma unroll
    for (int i=0;i<4;i++) { acc[i][0]=acc[i][1]=acc[i][2]=acc[i][3]=0.f;
                            accp[i][0]=accp[i][1]=accp[i][2]=accp[i][3]=0.f; }
    #pragma unroll 4
    for (int k = 0; k < 64; k++) {
        float4 a = *(const float4*)&As[k][rb];
        float4 b = *(const float4*)&Bs[k][cb];
        float ar[4] = {a.x,a.y,a.z,a.w}, br[4] = {b.x,b.y,b.z,b.w};
        #pragma unroll
        for (int i=0;i<4;i++)
            #pragma unroll
            for (int j=0;j<4;j++) acc[i][j] = fmaf(ar[i], br[j], acc[i][j]);
    }
    #pragma unroll
    for (int k = 0; k < 3; k++) {
        float4 a = *(const float4*)&P0[k][rb];
        float4 b = *(const float4*)&P1[k][cb];
        float ar[4] = {a.x,a.y,a.z,a.w}, br[4] = {b.x,b.y,b.z,b.w};
        #pragma unroll
        for (int i=0;i<4;i++)
            #pragma unroll
            for (int j=0;j<4;j++) accp[i][j] = fmaf(ar[i], br[j], accp[i][j]);
    }

    float eps = expf(epsilon[0]) + 0.025f;
    float inv_eps = 1.0f/eps;
    float cs[4] = {0.f,0.f,0.f,0.f};
    #pragma unroll
    for (int i = 0; i < 4; i++) {
        float n0v = N0s[rb+i];
        float kv[4];
        #pragma unroll
        for (int j = 0; j < 4; j++) {
            float sqd = n0v + N1s[cb+j] - 2.0f*accp[i][j];
            float Cv  = 1.0f - acc[i][j];
            float v   = (sqd < 100.0f) ? expf(-Cv*inv_eps) : 0.0f;
            kv[j] = v; cs[j] += v;
        }
        float4 o = make_float4(kv[0],kv[1],kv[2],kv[3]);
        *(float4*)&g_K[((size_t)(bz*NNPTS) + row0 + rb + i)*NNPTS + col0 + cb] = o;
    }
    #pragma unroll
    for (int j = 0; j < 4; j++) atomicAdd(&colpart[cb+j], cs[j]);
    __syncthreads();
    if (tid < 64) atomicAdd(&g_colsum[bz*NNPTS + col0 + tid], colpart[tid]);
}

// -------- b vector, stored transposed for rowpass ------------------------
__global__ __launch_bounds__(256)
void bvec_kernel(const float* __restrict__ pc1,
                 const float* __restrict__ gamma, const float* __restrict__ epsilon)
{
    int i = blockIdx.x*blockDim.x + threadIdx.x;
    if (i >= NTOT) return;
    float eps = expf(epsilon[0]) + 0.025f;
    float gam = expf(gamma[0]);
    float power = gam/(gam+eps);
    float kta = g_colsum[i] * (1.0f/NNPTS);
    float b = powf((1.0f/NNPTS)/(kta + 1e-8f), power);
    int bz = i / NNPTS, c = i % NNPTS;
    // transposed layout: slot for column c is (c&3)*1024 + (c>>2)
    g_w4t[bz*NNPTS + (c & 3)*1024 + (c >> 2)] =
        make_float4(b, b*pc1[i*3+0], b*pc1[i*3+1], b*pc1[i*3+2]);
}

// ---------------- row pass: Kb, K b pc1 -> ot_flow ------------------------
// grid = NTOT/4 blocks, 256 threads, 4 rows per block, no dynamic smem.
__global__ __launch_bounds__(256)
void rowpass_kernel(const float* __restrict__ pc0,
                    const float* __restrict__ gamma, const float* __restrict__ epsilon)
{
    __shared__ float rbuf[8][4][4];
    int tid = threadIdx.x;
    int r0 = blockIdx.x * 4;
    int bz = r0 / NNPTS;
    const float4* wt = g_w4t + bz*NNPTS;
    int wid = tid >> 5, lane = tid & 31;

    const float4* K0 = (const float4*)(g_K + (size_t)(r0+0)*NNPTS);
    const float4* K1 = (const float4*)(g_K + (size_t)(r0+1)*NNPTS);
    const float4* K2 = (const float4*)(g_K + (size_t)(r0+2)*NNPTS);
    const float4* K3 = (const float4*)(g_K + (size_t)(r0+3)*NNPTS);
    float acc[4][4];
    #pragma unroll
    for (int r = 0; r < 4; r++)
        acc[r][0]=acc[r][1]=acc[r][2]=acc[r][3]=0.f;
    #pragma unroll
    for (int i = 0; i < 4; i++) {
        int f = tid + i*256;
        float4 w0 = __ldg(&wt[f]),      w1 = __ldg(&wt[1024+f]);
        float4 w2 = __ldg(&wt[2048+f]), w3 = __ldg(&wt[3072+f]);
        float4 kr[4] = { K0[f], K1[f], K2[f], K3[f] };
        #pragma unroll
        for (int r = 0; r < 4; r++) {
            float4 k = kr[r];
            acc[r][0] = fmaf(k.x,w0.x, fmaf(k.y,w1.x, fmaf(k.z,w2.x, fmaf(k.w,w3.x, acc[r][0]))));
            acc[r][1] = fmaf(k.x,w0.y, fmaf(k.y,w1.y, fmaf(k.z,w2.y, fmaf(k.w,w3.y, acc[r][1]))));
            acc[r][2] = fmaf(k.x,w0.z, fmaf(k.y,w1.z, fmaf(k.z,w2.z, fmaf(k.w,w3.z, acc[r][2]))));
            acc[r][3] = fmaf(k.x,w0.w, fmaf(k.y,w1.w, fmaf(k.z,w2.w, fmaf(k.w,w3.w, acc[r][3]))));
        }
    }
    #pragma unroll
    for (int r = 0; r < 4; r++) {
        #pragma unroll
        for (int o = 16; o > 0; o >>= 1) {
            acc[r][0] += __shfl_xor_sync(0xffffffffu, acc[r][0], o);
            acc[r][1] += __shfl_xor_sync(0xffffffffu, acc[r][1], o);
            acc[r][2] += __shfl_xor_sync(0xffffffffu, acc[r][2], o);
            acc[r][3] += __shfl_xor_sync(0xffffffffu, acc[r][3], o);
        }
        if (lane == 0) {
            rbuf[wid][r][0]=acc[r][0]; rbuf[wid][r][1]=acc[r][1];
            rbuf[wid][r][2]=acc[r][2]; rbuf[wid][r][3]=acc[r][3];
        }
    }
    __syncthreads();
    if (tid < 4) {
        int r = tid;
        float Kb=0.f,Sx=0.f,Sy=0.f,Sz=0.f;
        #pragma unroll
        for (int w = 0; w < 8; w++) {
            Kb += rbuf[w][r][0]; Sx += rbuf[w][r][1];
            Sy += rbuf[w][r][2]; Sz += rbuf[w][r][3];
        }
        float eps = expf(epsilon[0]) + 0.025f;
        float gam = expf(gamma[0]);
        float power = gam/(gam+eps);
        float a  = powf((1.0f/NNPTS)/(Kb + 1e-8f), power);
        float rs = a*Kb;
        float inv = 1.0f/(rs + 1e-8f);
        int row = r0 + r;
        g_otflow[row*3+0] = a*Sx*inv - pc0[row*3+0];
        g_otflow[row*3+1] = a*Sy*inv - pc0[row*3+1];
        g_otflow[row*3+2] = a*Sz*inv - pc0[row*3+2];
    }
}

// ---------------- KNN: radix-select 32 smallest sqdists per row ----------
// 1 query per 256-thread block; per-warp hist + match_any aggregation +
// parallel 2-level scan (no serial thread-0 scan, no giant smem cache).
__global__ __launch_bounds__(256)
void knn_kernel(const float* __restrict__ pc0)
{
    __shared__ int s_hist[8][256];
    __shared__ int s_wsum[8];
    __shared__ unsigned s_prefix;
    __shared__ int s_krem, s_cl, s_ct;
    __shared__ int s_out[KNN];
    __shared__ int s_tie[64];

    int n = blockIdx.x; int bz = n / NNPTS; int nl = n % NNPTS;
    const float* pc = pc0 + bz*NNPTS*3;
    const float* n0 = g_n0 + bz*NNPTS;
    int tid = threadIdx.x;
    int wid = tid >> 5, lane = tid & 31;

    float qx = pc[nl*3+0], qy = pc[nl*3+1], qz = pc[nl*3+2];
    float qn = n0[nl];
    unsigned key[16];
    #pragma unroll
    for (int i = 0; i < 16; i++) {
        int m = tid + i*256;
        float px = pc[m*3+0], py = pc[m*3+1], pz = pc[m*3+2];
        float dot = px*qx + py*qy + pz*qz;
        float d = qn + n0[m] - 2.0f*dot;
        unsigned u = __float_as_uint(d);
        key[i] = (u & 0x80000000u) ? ~u : (u | 0x80000000u);
    }

    if (tid == 0) { s_prefix = 0u; s_krem = KNN; s_cl = 0; s_ct = 0; }

    for (int r = 0; r < 4; r++) {
        int shift = 24 - 8*r;
        #pragma unroll
        for (int w = 0; w < 8; w++) s_hist[w][tid] = 0;
        __syncthreads();
        unsigned pref = s_prefix;
        int krem = s_krem;
        unsigned msk = (r == 0) ? 0u : (0xFFFFFFFFu << (32 - 8*r));
        #pragma unroll
        for (int i = 0; i < 16; i++) {
            unsigned bin = (key[i] >> shift) & 255u;
            bool valid = ((key[i] & msk) == (pref & msk));
            unsigned tag = valid ? bin : (0x100u + (unsigned)lane);
            unsigned grp = __match_any_sync(0xffffffffu, tag);
            if (valid && lane == (__ffs(grp) - 1))
                atomicAdd(&s_hist[wid][bin], __popc(grp));
        }
        __syncthreads();
        // parallel scan over 256 bins (bin index = tid)
        int c = 0;
        #pragma unroll
        for (int w = 0; w < 8; w++) c += s_hist[w][tid];
        int v = c;
        #pragma unroll
        for (int o = 1; o < 32; o <<= 1) {
            int x = __shfl_up_sync(0xffffffffu, v, o);
            if (lane >= o) v += x;
        }
        if (lane == 31) s_wsum[wid] = v;
        __syncthreads();
        if (tid == 0) {
            int accum = 0;
            #pragma unroll
            for (int w = 0; w < 8; w++) { int t = s_wsum[w]; s_wsum[w] = accum; accum += t; }
        }
        __syncthreads();
        int incl = v + s_wsum[wid];
        int excl = incl - c;
        if (excl < krem && krem <= incl) {
            s_prefix = pref | ((unsigned)tid << shift);
            s_krem = krem - excl;
        }
        __syncthreads();
    }

    unsigned pivot = s_prefix;
    #pragma unroll
    for (int i = 0; i < 16; i++) {
        unsigned u = key[i];
        if (u < pivot)       { int p = atomicAdd(&s_cl, 1); s_out[p] = i*256 + tid; }
        else if (u == pivot) { int t = atomicAdd(&s_ct, 1); if (t < 64) s_tie[t] = i*256 + tid; }
    }
    __syncthreads();
    if (tid == 0) {
        int cl = s_cl;
        int nt = (s_ct < 64) ? s_ct : 64;
        int need = KNN - cl;                 // ties by lowest index (jax tie-break)
        for (int s = 0; s < need; s++) {
            int best = 0x7FFFFFFF, bi = 0;
            for (int t = 0; t < nt; t++) if (s_tie[t] < best) { best = s_tie[t]; bi = t; }
            s_tie[bi] = 0x7FFFFFFF;
            s_out[cl + s] = best;
        }
    }
    __syncthreads();
    if (tid < KNN) g_idx[n*KNN + tid] = s_out[tid];
}

// ---------------- fused set-conv layer (edge GEMM + max + 2 dense) -------
__device__ __forceinline__ float lrelu(float x){ return (x > 0.f) ? x : 0.1f*x; }

template<int LAYER>
__global__ __launch_bounds__(128)
void conv_kernel(const float* __restrict__ pc0,
                 const float* __restrict__ W1, const float* __restrict__ B1,
                 const float* __restrict__ W2, const float* __restrict__ B2,
                 const float* __restrict__ W3, const float* __restrict__ B3,
                 const float* __restrict__ Wfc, const float* __restrict__ Bfc,
                 float* __restrict__ dout)
{
    constexpr int CIN  = (LAYER==0) ? 3 : (LAYER==1) ? 32 : 64;
    constexpr int C    = (LAYER==0) ? 32 : (LAYER==1) ? 64 : 128;
    constexpr bool FIN = (LAYER==2);
    constexpr int NPB  = 128 / C;
    constexpr int KTOT = CIN + 3;
    constexpr int K4   = (KTOT + 3) & ~3;
    constexpr int KM   = KTOT & ~3;

    __shared__ __align__(16) float in_s[NPB][KNN][K4];
    __shared__ float h1[NPB][C];
    __shared__ float h2[NPB][C];
    __shared__ int   nb_s[NPB][KNN];

    const float* feat_in = (LAYER==0) ? g_otflow : (LAYER==1) ? g_x1 : g_x2;
    float* feat_out = (LAYER==0) ? g_x1 : g_x2;

    int tid = threadIdx.x;
    int g = tid / C, c = tid % C;
    int node = blockIdx.x * NPB + g;
    int b = node / NNPTS;

    if (c < KNN) nb_s[g][c] = g_idx[node*KNN + c];
    __syncthreads();

    for (int e = c; e < KNN*KTOT; e += C) {
        int j = e / KTOT, k = e % KTOT;
        int nb = nb_s[g][j];
        float v;
        if (k < CIN) v = feat_in[(size_t)(b*NNPTS + nb)*CIN + k];
        else {
            int d = k - CIN;
            v = pc0[(b*NNPTS + nb)*3 + d] - pc0[node*3 + d];
        }
        in_s[g][j][k] = v;
    }
    __syncthreads();

    // edge layer: acc over KNN neighbors, channel c
    float acc[KNN];
    float bias1 = B1[c];
    #pragma unroll
    for (int j = 0; j < KNN; j++) acc[j] = bias1;
    for (int k = 0; k < KM; k += 4) {
        float w0 = W1[(k+0)*C + c];
        float w1 = W1[(k+1)*C + c];
        float w2 = W1[(k+2)*C + c];
        float w3 = W1[(k+3)*C + c];
        #pragma unroll
        for (int j = 0; j < KNN; j++) {
            float4 iv = *(const float4*)&in_s[g][j][k];
            acc[j] = fmaf(iv.x, w0, acc[j]);
            acc[j] = fmaf(iv.y, w1, acc[j]);
            acc[j] = fmaf(iv.z, w2, acc[j]);
            acc[j] = fmaf(iv.w, w3, acc[j]);
        }
    }
    for (int k = KM; k < KTOT; k++) {
        float w = W1[k*C + c];
        #pragma unroll
        for (int j = 0; j < KNN; j++) acc[j] = fmaf(in_s[g][j][k], w, acc[j]);
    }
    float mx = -3.4e38f;
    #pragma unroll
    for (int j = 0; j < KNN; j++) mx = fmaxf(mx, lrelu(acc[j]));
    h1[g][c] = mx;
    __syncthreads();

    float a2 = B2[c];
    for (int k = 0; k < C; k++) a2 = fmaf(h1[g][k], W2[k*C + c], a2);
    a2 = lrelu(a2);
    h2[g][c] = a2;
    __syncthreads();

    float a3 = B3[c];
    for (int k = 0; k < C; k++) a3 = fmaf(h2[g][k], W3[k*C + c], a3);
    a3 = lrelu(a3);

    if (!FIN) {
        feat_out[(size_t)node*C + c] = a3;
    } else {
        h1[g][c] = a3;
        __syncthreads();
        if (c < 3) {
            float o = Bfc[c];
            for (int k = 0; k < C; k++) o = fmaf(h1[g][k], Wfc[k*3 + c], o);
            dout[node*3 + c] = g_otflow[node*3 + c] + o;
        }
    }
}

// ---------------- launch --------------------------------------------------
extern "C" void kernel_launch(void* const* d_in, const int* in_sizes, int n_in,
                              void* d_out, int out_size)
{
    const float* pc0   = (const float*)d_in[0];
    const float* pc1   = (const float*)d_in[1];
    const float* f0    = (const float*)d_in[2];
    const float* f1    = (const float*)d_in[3];
    const float* gamma = (const float*)d_in[4];
    const float* eps   = (const float*)d_in[5];
    const float* w1_1=(const float*)d_in[6],  *b1_1=(const float*)d_in[7];
    const float* w1_2=(const float*)d_in[8],  *b1_2=(const float*)d_in[9];
    const float* w1_3=(const float*)d_in[10], *b1_3=(const float*)d_in[11];
    const float* w2_1=(const float*)d_in[12], *b2_1=(const float*)d_in[13];
    const float* w2_2=(const float*)d_in[14], *b2_2=(const float*)d_in[15];
    const float* w2_3=(const float*)d_in[16], *b2_3=(const float*)d_in[17];
    const float* w3_1=(const float*)d_in[18], *b3_1=(const float*)d_in[19];
    const float* w3_2=(const float*)d_in[20], *b3_2=(const float*)d_in[21];
    const float* w3_3=(const float*)d_in[22], *b3_3=(const float*)d_in[23];
    const float* wfc =(const float*)d_in[24], *bfc =(const float*)d_in[25];
    float* out = (float*)d_out;

    prep_kernel<<<2048, 256>>>(pc0, pc1, f0, f1);
    kmat_kernel<<<dim3(NNPTS/64, NNPTS/64, BB), 256>>>(pc0, pc1, eps);
    bvec_kernel<<<(NTOT + 255)/256, 256>>>(pc1, gamma, eps);
    rowpass_kernel<<<NTOT/4, 256>>>(pc0, gamma, eps);
    knn_kernel<<<NTOT, 256>>>(pc0);
    conv_kernel<0><<<NTOT/4, 128>>>(pc0, w1_1,b1_1, w1_2,b1_2, w1_3,b1_3, wfc,bfc, out);
    conv_kernel<1><<<NTOT/2, 128>>>(pc0, w2_1,b2_1, w2_2,b2_2, w2_3,b2_3, wfc,bfc, out);
    conv_kernel<2><<<NTOT,   128>>>(pc0, w3_1,b3_1, w3_2,b3_2, w3_3,b3_3, wfc,bfc, out);
}

// round 4
// speedup vs baseline: 2.0025x; 1.7897x over previous
#include <cuda_runtime.h>
#include <math.h>
#include <stdint.h>

#define BB 2
#define NNPTS 4096
#define CF 64
#define KNN 32
#define NTOT (BB*NNPTS)

// ---------------- scratch (static __device__, no allocs) ----------------
__device__ float  g_K[(size_t)BB*NNPTS*NNPTS];   // 128 MB transport kernel
__device__ float  g_f0n[NTOT*CF];
__device__ float  g_f1n[NTOT*CF];
__device__ float  g_n0[NTOT];
__device__ float  g_n1[NTOT];
__device__ float  g_colsum[NTOT];
__device__ float4 g_w4t[NTOT];                   // transposed (b, b*x, b*y, b*z)
__device__ float  g_otflow[NTOT*3];
__device__ int    g_idx[NTOT*KNN];
__device__ float  g_x1[NTOT*32];
__device__ float  g_x2[NTOT*64];

// ---- FMA-only exp (no MUFU): exp(x) = 2^(x*log2e), degree-6 poly --------
__device__ __forceinline__ float fexp(float x)
{
    float y = fmaf(x, 1.442695040888963f, 0.0f);
    y = fmaxf(y, -125.0f);
    float r = floorf(y);
    float f = y - r;                       // [0,1)
    float p = 1.5403530e-4f;               // Taylor of 2^f
    p = fmaf(p, f, 1.3333558e-3f);
    p = fmaf(p, f, 9.6181291e-3f);
    p = fmaf(p, f, 5.5504109e-2f);
    p = fmaf(p, f, 2.4022651e-1f);
    p = fmaf(p, f, 6.9314718e-1f);
    p = fmaf(p, f, 1.0f);
    return __int_as_float(__float_as_int(p) + (((int)r) << 23));
}

// ---------------- prep: feature normalize, point norms, colsum zero -----
__global__ __launch_bounds__(256)
void prep_kernel(const float* __restrict__ pc0, const float* __restrict__ pc1,
                 const float* __restrict__ f0, const float* __restrict__ f1)
{
    int w    = (blockIdx.x*blockDim.x + threadIdx.x) >> 5;
    int lane = threadIdx.x & 31;
    if (w >= 2*NTOT) return;
    int which = w / NTOT;       // 0: feats0, 1: feats1
    int row   = w % NTOT;
    const float* f = which ? f1 : f0;
    float v0 = f[row*CF + lane];
    float v1 = f[row*CF + 32 + lane];
    float ss = v0*v0 + v1*v1;
    #pragma unroll
    for (int o = 16; o > 0; o >>= 1) ss += __shfl_xor_sync(0xffffffffu, ss, o);
    float inv = rsqrtf(ss + 1e-8f);
    float* out = which ? g_f1n : g_f0n;
    out[row*CF + lane]      = v0*inv;
    out[row*CF + 32 + lane] = v1*inv;
    if (lane == 0) {
        const float* pc = which ? pc1 : pc0;
        float x = pc[row*3+0], y = pc[row*3+1], z = pc[row*3+2];
        float n2 = x*x + y*y + z*z;
        if (which) g_n1[row] = n2;
        else { g_n0[row] = n2; g_colsum[row] = 0.f; }
    }
}

// ---------------- K = exp(-(1 - f0n.f1n)/eps) * (sqdist<100), + colsums --
__global__ __launch_bounds__(256)
void kmat_kernel(const float* __restrict__ pc0, const float* __restrict__ pc1,
                 const float* __restrict__ epsilon)
{
    __shared__ float As[64][64];   // k-major: As[k][row]
    __shared__ float Bs[64][64];
    __shared__ float P0[3][64], P1[3][64];
    __shared__ float N0s[64], N1s[64];
    __shared__ float colpart[64];

    int bz = blockIdx.z;
    int row0 = blockIdx.y*64, col0 = blockIdx.x*64;
    int tid = threadIdx.x;

    {   // feature tiles, transpose into k-major smem
        int r = tid & 63, q = tid >> 6;                 // q in 0..3
        const float* a = g_f0n + (size_t)(bz*NNPTS + row0 + r)*CF + q*16;
        const float* b = g_f1n + (size_t)(bz*NNPTS + col0 + r)*CF + q*16;
        #pragma unroll
        for (int i = 0; i < 4; i++) {
            float4 va = *(const float4*)(a + 4*i);
            float4 vb = *(const float4*)(b + 4*i);
            int k = q*16 + 4*i;
            As[k+0][r]=va.x; As[k+1][r]=va.y; As[k+2][r]=va.z; As[k+3][r]=va.w;
            Bs[k+0][r]=vb.x; Bs[k+1][r]=vb.y; Bs[k+2][r]=vb.z; Bs[k+3][r]=vb.w;
        }
    }
    if (tid < 64) {
        int r = tid;
        #pragma unroll
        for (int d = 0; d < 3; d++) P0[d][r] = pc0[(bz*NNPTS+row0+r)*3 + d];
        N0s[r] = g_n0[bz*NNPTS + row0 + r];
        colpart[r] = 0.f;
    } else if (tid < 128) {
        int r = tid - 64;
        #pragma unroll
        for (int d = 0; d < 3; d++) P1[d][r] = pc1[(bz*NNPTS+col0+r)*3 + d];
        N1s[r] = g_n1[bz*NNPTS + col0 + r];
    }
    __syncthreads();

    int rb = (tid >> 4)*4, cb = (tid & 15)*4;
    float acc[4][4];  float accp[4][4];
    #pragma unroll
    for (int i=0;i<4;i++) { acc[i][0]=acc[i][1]=acc[i][2]=acc[i][3]=0.f;
                            accp[i][0]=accp[i][1]=accp[i][2]=accp[i][3]=0.f; }
    #pragma unroll 4
    for (int k = 0; k < 64; k++) {
        float4 a = *(const float4*)&As[k][rb];
        float4 b = *(const float4*)&Bs[k][cb];
        float ar[4] = {a.x,a.y,a.z,a.w}, br[4] = {b.x,b.y,b.z,b.w};
        #pragma unroll
        for (int i=0;i<4;i++)
            #pragma unroll
            for (int j=0;j<4;j++) acc[i][j] = fmaf(ar[i], br[j], acc[i][j]);
    }
    #pragma unroll
    for (int k = 0; k < 3; k++) {
        float4 a = *(const float4*)&P0[k][rb];
        float4 b = *(const float4*)&P1[k][cb];
        float ar[4] = {a.x,a.y,a.z,a.w}, br[4] = {b.x,b.y,b.z,b.w};
        #pragma unroll
        for (int i=0;i<4;i++)
            #pragma unroll
            for (int j=0;j<4;j++) accp[i][j] = fmaf(ar[i], br[j], accp[i][j]);
    }

    float eps = fexp(epsilon[0]) + 0.025f;
    float inv_eps = 1.0f/eps;
    float cs[4] = {0.f,0.f,0.f,0.f};
    #pragma unroll
    for (int i = 0; i < 4; i++) {
        float n0v = N0s[rb+i];
        float kv[4];
        #pragma unroll
        for (int j = 0; j < 4; j++) {
            float sqd = n0v + N1s[cb+j] - 2.0f*accp[i][j];
            float Cv  = 1.0f - acc[i][j];
            float v   = (sqd < 100.0f) ? fexp(-Cv*inv_eps) : 0.0f;
            kv[j] = v; cs[j] += v;
        }
        float4 o = make_float4(kv[0],kv[1],kv[2],kv[3]);
        *(float4*)&g_K[((size_t)(bz*NNPTS) + row0 + rb + i)*NNPTS + col0 + cb] = o;
    }
    #pragma unroll
    for (int j = 0; j < 4; j++) atomicAdd(&colpart[cb+j], cs[j]);
    __syncthreads();
    if (tid < 64) atomicAdd(&g_colsum[bz*NNPTS + col0 + tid], colpart[tid]);
}

// -------- b vector, stored transposed for rowpass ------------------------
__global__ __launch_bounds__(256)
void bvec_kernel(const float* __restrict__ pc1,
                 const float* __restrict__ gamma, const float* __restrict__ epsilon)
{
    int i = blockIdx.x*blockDim.x + threadIdx.x;
    if (i >= NTOT) return;
    float eps = expf(epsilon[0]) + 0.025f;
    float gam = expf(gamma[0]);
    float power = gam/(gam+eps);
    float kta = g_colsum[i] * (1.0f/NNPTS);
    float b = powf((1.0f/NNPTS)/(kta + 1e-8f), power);
    int bz = i / NNPTS, c = i % NNPTS;
    // transposed layout: slot for column c is (c&3)*1024 + (c>>2)
    g_w4t[bz*NNPTS + (c & 3)*1024 + (c >> 2)] =
        make_float4(b, b*pc1[i*3+0], b*pc1[i*3+1], b*pc1[i*3+2]);
}

// ---------------- row pass: Kb, K b pc1 -> ot_flow ------------------------
// grid = NTOT/4 blocks, 256 threads, 4 rows per block, no dynamic smem.
__global__ __launch_bounds__(256)
void rowpass_kernel(const float* __restrict__ pc0,
                    const float* __restrict__ gamma, const float* __restrict__ epsilon)
{
    __shared__ float rbuf[8][4][4];
    int tid = threadIdx.x;
    int r0 = blockIdx.x * 4;
    int bz = r0 / NNPTS;
    const float4* wt = g_w4t + bz*NNPTS;
    int wid = tid >> 5, lane = tid & 31;

    const float4* K0 = (const float4*)(g_K + (size_t)(r0+0)*NNPTS);
    const float4* K1 = (const float4*)(g_K + (size_t)(r0+1)*NNPTS);
    const float4* K2 = (const float4*)(g_K + (size_t)(r0+2)*NNPTS);
    const float4* K3 = (const float4*)(g_K + (size_t)(r0+3)*NNPTS);
    float acc[4][4];
    #pragma unroll
    for (int r = 0; r < 4; r++)
        acc[r][0]=acc[r][1]=acc[r][2]=acc[r][3]=0.f;
    #pragma unroll
    for (int i = 0; i < 4; i++) {
        int f = tid + i*256;
        float4 w0 = __ldg(&wt[f]),      w1 = __ldg(&wt[1024+f]);
        float4 w2 = __ldg(&wt[2048+f]), w3 = __ldg(&wt[3072+f]);
        float4 kr[4] = { K0[f], K1[f], K2[f], K3[f] };
        #pragma unroll
        for (int r = 0; r < 4; r++) {
            float4 k = kr[r];
            acc[r][0] = fmaf(k.x,w0.x, fmaf(k.y,w1.x, fmaf(k.z,w2.x, fmaf(k.w,w3.x, acc[r][0]))));
            acc[r][1] = fmaf(k.x,w0.y, fmaf(k.y,w1.y, fmaf(k.z,w2.y, fmaf(k.w,w3.y, acc[r][1]))));
            acc[r][2] = fmaf(k.x,w0.z, fmaf(k.y,w1.z, fmaf(k.z,w2.z, fmaf(k.w,w3.z, acc[r][2]))));
            acc[r][3] = fmaf(k.x,w0.w, fmaf(k.y,w1.w, fmaf(k.z,w2.w, fmaf(k.w,w3.w, acc[r][3]))));
        }
    }
    #pragma unroll
    for (int r = 0; r < 4; r++) {
        #pragma unroll
        for (int o = 16; o > 0; o >>= 1) {
            acc[r][0] += __shfl_xor_sync(0xffffffffu, acc[r][0], o);
            acc[r][1] += __shfl_xor_sync(0xffffffffu, acc[r][1], o);
            acc[r][2] += __shfl_xor_sync(0xffffffffu, acc[r][2], o);
            acc[r][3] += __shfl_xor_sync(0xffffffffu, acc[r][3], o);
        }
        if (lane == 0) {
            rbuf[wid][r][0]=acc[r][0]; rbuf[wid][r][1]=acc[r][1];
            rbuf[wid][r][2]=acc[r][2]; rbuf[wid][r][3]=acc[r][3];
        }
    }
    __syncthreads();
    if (tid < 4) {
        int r = tid;
        float Kb=0.f,Sx=0.f,Sy=0.f,Sz=0.f;
        #pragma unroll
        for (int w = 0; w < 8; w++) {
            Kb += rbuf[w][r][0]; Sx += rbuf[w][r][1];
            Sy += rbuf[w][r][2]; Sz += rbuf[w][r][3];
        }
        float eps = expf(epsilon[0]) + 0.025f;
        float gam = expf(gamma[0]);
        float power = gam/(gam+eps);
        float a  = powf((1.0f/NNPTS)/(Kb + 1e-8f), power);
        float rs = a*Kb;
        float inv = 1.0f/(rs + 1e-8f);
        int row = r0 + r;
        g_otflow[row*3+0] = a*Sx*inv - pc0[row*3+0];
        g_otflow[row*3+1] = a*Sy*inv - pc0[row*3+1];
        g_otflow[row*3+2] = a*Sz*inv - pc0[row*3+2];
    }
}

// ---------------- KNN: radix-select 32 smallest sqdists per row ----------
// (round-1 version: empirically the fastest variant)
__global__ __launch_bounds__(256)
void knn_kernel(const float* __restrict__ pc0)
{
    int n = blockIdx.x; int b = n / NNPTS; int nl = n % NNPTS;
    const float* pc = pc0 + b*NNPTS*3;
    const float* n0 = g_n0 + b*NNPTS;
    int tid = threadIdx.x;
    float qx = pc[nl*3+0], qy = pc[nl*3+1], qz = pc[nl*3+2];
    float qn = n0[nl];
    unsigned key[16];
    #pragma unroll
    for (int i = 0; i < 16; i++) {
        int m = tid + i*256;
        float px = pc[m*3+0], py = pc[m*3+1], pz = pc[m*3+2];
        float dot = px*qx + py*qy + pz*qz;
        float d = qn + n0[m] - 2.0f*dot;
        unsigned u = __float_as_uint(d);
        u = (u & 0x80000000u) ? ~u : (u | 0x80000000u);
        key[i] = u;
    }
    __shared__ int hist[256];
    __shared__ unsigned s_prefix;
    __shared__ int s_krem, s_cl, s_ct;
    __shared__ int s_out[KNN];
    __shared__ int s_tie[64];
    if (tid == 0) { s_prefix = 0u; s_krem = KNN; s_cl = 0; s_ct = 0; }
    for (int r = 0; r < 4; r++) {
        int shift = 24 - 8*r;
        hist[tid] = 0;
        __syncthreads();
        unsigned pref = s_prefix;
        unsigned msk  = (r == 0) ? 0u : (0xFFFFFFFFu << (32 - 8*r));
        #pragma unroll
        for (int i = 0; i < 16; i++)
            if ((key[i] & msk) == (pref & msk))
                atomicAdd(&hist[(key[i] >> shift) & 255], 1);
        __syncthreads();
        if (tid == 0) {
            int krem = s_krem, cum = 0, d = 0;
            for (; d < 256; d++) { int c = hist[d]; if (cum + c >= krem) break; cum += c; }
            s_prefix = pref | ((unsigned)d << shift);
            s_krem = krem - cum;
        }
        __syncthreads();
    }
    unsigned pivot = s_prefix;
    #pragma unroll
    for (int i = 0; i < 16; i++) {
        unsigned u = key[i];
        if (u < pivot)       { int p = atomicAdd(&s_cl, 1); s_out[p] = tid + i*256; }
        else if (u == pivot) { int t = atomicAdd(&s_ct, 1); if (t < 64) s_tie[t] = tid + i*256; }
    }
    __syncthreads();
    if (tid == 0) {
        int cl = s_cl;
        int nt = (s_ct < 64) ? s_ct : 64;
        int need = KNN - cl;                 // ties filled by lowest index (jax tie-break)
        for (int s = 0; s < need; s++) {
            int best = 0x7FFFFFFF, bi = 0;
            for (int t = 0; t < nt; t++) if (s_tie[t] < best) { best = s_tie[t]; bi = t; }
            s_tie[bi] = 0x7FFFFFFF;
            s_out[cl + s] = best;
        }
    }
    __syncthreads();
    if (tid < KNN) g_idx[n*KNN + tid] = s_out[tid];
}

// ---------------- fused set-conv layer (edge GEMM + max + 2 dense) -------
__device__ __forceinline__ float lrelu(float x){ return (x > 0.f) ? x : 0.1f*x; }

template<int LAYER>
__global__ __launch_bounds__(128)
void conv_kernel(const float* __restrict__ pc0,
                 const float* __restrict__ W1, const float* __restrict__ B1,
                 const float* __restrict__ W2, const float* __restrict__ B2,
                 const float* __restrict__ W3, const float* __restrict__ B3,
                 const float* __restrict__ Wfc, const float* __restrict__ Bfc,
                 float* __restrict__ dout)
{
    constexpr int CIN  = (LAYER==0) ? 3 : (LAYER==1) ? 32 : 64;
    constexpr int C    = (LAYER==0) ? 32 : (LAYER==1) ? 64 : 128;
    constexpr bool FIN = (LAYER==2);
    constexpr int NPB  = 128 / C;
    constexpr int KTOT = CIN + 3;
    constexpr int K4   = (KTOT + 3) & ~3;
    constexpr int KM   = KTOT & ~3;

    __shared__ __align__(16) float in_s[NPB][KNN][K4];
    __shared__ float h1[NPB][C];
    __shared__ float h2[NPB][C];
    __shared__ int   nb_s[NPB][KNN];

    const float* feat_in = (LAYER==0) ? g_otflow : (LAYER==1) ? g_x1 : g_x2;
    float* feat_out = (LAYER==0) ? g_x1 : g_x2;

    int tid = threadIdx.x;
    int g = tid / C, c = tid % C;
    int node = blockIdx.x * NPB + g;
    int b = node / NNPTS;

    if (c < KNN) nb_s[g][c] = g_idx[node*KNN + c];
    __syncthreads();

    for (int e = c; e < KNN*KTOT; e += C) {
        int j = e / KTOT, k = e % KTOT;
        int nb = nb_s[g][j];
        float v;
        if (k < CIN) v = feat_in[(size_t)(b*NNPTS + nb)*CIN + k];
        else {
            int d = k - CIN;
            v = pc0[(b*NNPTS + nb)*3 + d] - pc0[node*3 + d];
        }
        in_s[g][j][k] = v;
    }
    __syncthreads();

    // edge layer: acc over KNN neighbors, channel c
    float acc[KNN];
    float bias1 = B1[c];
    #pragma unroll
    for (int j = 0; j < KNN; j++) acc[j] = bias1;
    for (int k = 0; k < KM; k += 4) {
        float w0 = W1[(k+0)*C + c];
        float w1 = W1[(k+1)*C + c];
        float w2 = W1[(k+2)*C + c];
        float w3 = W1[(k+3)*C + c];
        #pragma unroll
        for (int j = 0; j < KNN; j++) {
            float4 iv = *(const float4*)&in_s[g][j][k];
            acc[j] = fmaf(iv.x, w0, acc[j]);
            acc[j] = fmaf(iv.y, w1, acc[j]);
            acc[j] = fmaf(iv.z, w2, acc[j]);
            acc[j] = fmaf(iv.w, w3, acc[j]);
        }
    }
    for (int k = KM; k < KTOT; k++) {
        float w = W1[k*C + c];
        #pragma unroll
        for (int j = 0; j < KNN; j++) acc[j] = fmaf(in_s[g][j][k], w, acc[j]);
    }
    float mx = -3.4e38f;
    #pragma unroll
    for (int j = 0; j < KNN; j++) mx = fmaxf(mx, lrelu(acc[j]));
    h1[g][c] = mx;
    __syncthreads();

    float a2 = B2[c];
    for (int k = 0; k < C; k++) a2 = fmaf(h1[g][k], W2[k*C + c], a2);
    a2 = lrelu(a2);
    h2[g][c] = a2;
    __syncthreads();

    float a3 = B3[c];
    for (int k = 0; k < C; k++) a3 = fmaf(h2[g][k], W3[k*C + c], a3);
    a3 = lrelu(a3);

    if (!FIN) {
        feat_out[(size_t)node*C + c] = a3;
    } else {
        h1[g][c] = a3;
        __syncthreads();
        if (c < 3) {
            float o = Bfc[c];
            for (int k = 0; k < C; k++) o = fmaf(h1[g][k], Wfc[k*3 + c], o);
            dout[node*3 + c] = g_otflow[node*3 + c] + o;
        }
    }
}

// ---------------- launch --------------------------------------------------
extern "C" void kernel_launch(void* const* d_in, const int* in_sizes, int n_in,
                              void* d_out, int out_size)
{
    const float* pc0   = (const float*)d_in[0];
    const float* pc1   = (const float*)d_in[1];
    const float* f0    = (const float*)d_in[2];
    const float* f1    = (const float*)d_in[3];
    const float* gamma = (const float*)d_in[4];
    const float* eps   = (const float*)d_in[5];
    const float* w1_1=(const float*)d_in[6],  *b1_1=(const float*)d_in[7];
    const float* w1_2=(const float*)d_in[8],  *b1_2=(const float*)d_in[9];
    const float* w1_3=(const float*)d_in[10], *b1_3=(const float*)d_in[11];
    const float* w2_1=(const float*)d_in[12], *b2_1=(const float*)d_in[13];
    const float* w2_2=(const float*)d_in[14], *b2_2=(const float*)d_in[15];
    const float* w2_3=(const float*)d_in[16], *b2_3=(const float*)d_in[17];
    const float* w3_1=(const float*)d_in[18], *b3_1=(const float*)d_in[19];
    const float* w3_2=(const float*)d_in[20], *b3_2=(const float*)d_in[21];
    const float* w3_3=(const float*)d_in[22], *b3_3=(const float*)d_in[23];
    const float* wfc =(const float*)d_in[24], *bfc =(const float*)d_in[25];
    float* out = (float*)d_out;

    prep_kernel<<<2048, 256>>>(pc0, pc1, f0, f1);
    kmat_kernel<<<dim3(NNPTS/64, NNPTS/64, BB), 256>>>(pc0, pc1, eps);
    bvec_kernel<<<(NTOT + 255)/256, 256>>>(pc1, gamma, eps);
    rowpass_kernel<<<NTOT/4, 256>>>(pc0, gamma, eps);
    knn_kernel<<<NTOT, 256>>>(pc0);
    conv_kernel<0><<<NTOT/4, 128>>>(pc0, w1_1,b1_1, w1_2,b1_2, w1_3,b1_3, wfc,bfc, out);
    conv_kernel<1><<<NTOT/2, 128>>>(pc0, w2_1,b2_1, w2_2,b2_2, w2_3,b2_3, wfc,bfc, out);
    conv_kernel<2><<<NTOT,   128>>>(pc0, w3_1,b3_1, w3_2,b3_2, w3_3,b3_3, wfc,bfc, out);
}